// round 2
// baseline (speedup 1.0000x reference)
#include <cuda_runtime.h>

#define MAX_PBLOCKS 1024
__device__ float g_partials[MAX_PBLOCKS];

// Kernel 1 (vectorized): each thread processes 4 consecutive elements.
// v = mean_b x[b,i]; bin via binary search on min_vals (shared); gather weight;
// block-reduce; one partial per block.
__global__ void ril_reduce_kernel(const float* __restrict__ x,
                                  const float* __restrict__ weights,
                                  const float* __restrict__ min_vals,
                                  const float* __restrict__ max_vals,
                                  const int* __restrict__ start_pos,
                                  const int* __restrict__ offsets,
                                  const int* __restrict__ sizes,
                                  int B, int D, int G, int Wn)
{
    extern __shared__ char smem_raw[];
    float* smv = (float*)smem_raw;              // G
    float* smx = smv + G;                       // G
    int*   ssp = (int*)(smx + G);               // G
    int*   sof = ssp + G;                       // G
    int*   ssz = sof + G;                       // G
    for (int i = threadIdx.x; i < G; i += blockDim.x) {
        smv[i] = min_vals[i];
        smx[i] = max_vals[i];
        ssp[i] = start_pos[i];
        sof[i] = offsets[i];
        ssz[i] = sizes[i];
    }
    __syncthreads();

    int t  = blockIdx.x * blockDim.x + threadIdx.x;
    int i0 = t * 4;
    float acc = 0.0f;
    float inv_b = 1.0f / (float)B;

    if (i0 + 3 < D) {
        float4 s4 = make_float4(0.f, 0.f, 0.f, 0.f);
        #pragma unroll 8
        for (int b = 0; b < B; ++b) {
            const float4 xv = *(const float4*)(x + (size_t)b * D + i0);
            s4.x += xv.x; s4.y += xv.y; s4.z += xv.z; s4.w += xv.w;
        }
        float v[4] = { s4.x * inv_b, s4.y * inv_b, s4.z * inv_b, s4.w * inv_b };
        #pragma unroll
        for (int k = 0; k < 4; ++k) {
            float vv = v[k];
            int lo = 0, hi = G;
            while (lo < hi) {
                int mid = (lo + hi) >> 1;
                if (smv[mid] <= vv) lo = mid + 1; else hi = mid;
            }
            int g  = lo - 1;
            int gc = min(max(g, 0), G - 1);
            bool in_range = (g >= 0) && (vv >= smv[gc]) && (vv <= smx[gc]);
            int pos = (i0 + k) - ssp[gc];
            bool valid = in_range && (pos >= 0) && (pos < ssz[gc]);
            int widx = sof[gc] + pos;
            widx = min(max(widx, 0), Wn - 1);
            float w = valid ? weights[widx] : 0.0f;
            acc += vv * w;
        }
    } else {
        // scalar tail (also covers non-multiple-of-4 D generally)
        for (int i = i0; i < min(i0 + 4, D); ++i) {
            float s = 0.0f;
            for (int b = 0; b < B; ++b) s += x[(size_t)b * D + i];
            float vv = s * inv_b;
            int lo = 0, hi = G;
            while (lo < hi) {
                int mid = (lo + hi) >> 1;
                if (smv[mid] <= vv) lo = mid + 1; else hi = mid;
            }
            int g  = lo - 1;
            int gc = min(max(g, 0), G - 1);
            bool in_range = (g >= 0) && (vv >= smv[gc]) && (vv <= smx[gc]);
            int pos = i - ssp[gc];
            bool valid = in_range && (pos >= 0) && (pos < ssz[gc]);
            int widx = sof[gc] + pos;
            widx = min(max(widx, 0), Wn - 1);
            float w = valid ? weights[widx] : 0.0f;
            acc += vv * w;
        }
    }

    // Block reduction
    #pragma unroll
    for (int o = 16; o > 0; o >>= 1)
        acc += __shfl_down_sync(0xffffffffu, acc, o);
    __shared__ float red[32];
    int lane = threadIdx.x & 31;
    int wid  = threadIdx.x >> 5;
    if (lane == 0) red[wid] = acc;
    __syncthreads();
    if (wid == 0) {
        int nwarps = (blockDim.x + 31) >> 5;
        acc = (lane < nwarps) ? red[lane] : 0.0f;
        #pragma unroll
        for (int o = 16; o > 0; o >>= 1)
            acc += __shfl_down_sync(0xffffffffu, acc, o);
        if (lane == 0) g_partials[blockIdx.x] = acc;
    }
}

// Kernel 2: every block redundantly reduces the partials (L2-resident),
// then writes its slice of the output. out_mask is int32 (bool stored as 4B).
__global__ void ril_finalize_kernel(const int* __restrict__ out_mask,
                                    float* __restrict__ out,
                                    int nPartials, int OUTN, int total)
{
    __shared__ float sp[MAX_PBLOCKS > 256 ? 256 : MAX_PBLOCKS];
    __shared__ float s_val;
    // nPartials <= 256 here
    if (threadIdx.x < nPartials) sp[threadIdx.x] = g_partials[threadIdx.x];
    __syncthreads();
    if (threadIdx.x == 0) {
        float s = 0.0f;
        for (int k = 0; k < nPartials; ++k) s += sp[k];
        s_val = s;
    }
    __syncthreads();
    float s = s_val;
    int j = blockIdx.x * blockDim.x + threadIdx.x;
    if (j < total) {
        float o = 0.0f;
        if (j < OUTN) o = (out_mask[j] != 0) ? s : 0.0f;
        out[j] = o;
    }
}

extern "C" void kernel_launch(void* const* d_in, const int* in_sizes, int n_in,
                              void* d_out, int out_size)
{
    const float* x        = (const float*)d_in[0];
    const float* weights  = (const float*)d_in[1];
    const float* min_vals = (const float*)d_in[2];
    const float* max_vals = (const float*)d_in[3];
    const int*   start_p  = (const int*)d_in[4];
    const int*   offsets  = (const int*)d_in[5];
    const int*   sizes    = (const int*)d_in[6];
    const int*   out_mask = (const int*)d_in[7];
    float* out = (float*)d_out;

    int G  = in_sizes[2];
    int Wn = in_sizes[1];
    int D  = Wn / G;
    int B  = in_sizes[0] / D;
    int OUTN = in_sizes[7];

    int threads = 256;
    int per_block = threads * 4;
    int blocks = (D + per_block - 1) / per_block;   // 64 for D=65536
    if (blocks > 256) blocks = 256;                 // cap (not hit for this shape)
    size_t shmem = (size_t)G * (2 * sizeof(float) + 3 * sizeof(int));

    ril_reduce_kernel<<<blocks, threads, shmem>>>(
        x, weights, min_vals, max_vals, start_p, offsets, sizes, B, D, G, Wn);

    int fthreads = 1024;
    int fblocks = (out_size + fthreads - 1) / fthreads;
    ril_finalize_kernel<<<fblocks, fthreads>>>(out_mask, out, blocks, OUTN, out_size);
}